// round 11
// baseline (speedup 1.0000x reference)
#include <cuda_runtime.h>
#include <cuda_pipeline_primitives.h>

// x (B=8, S=4096, D=1024) fp32. Stats from sequential scan over D of x[0]:
//   m_i = (m_{i-1} + d_i)/i ;  v += (d_i - m_i)^2 ;  var = v/(D-1)
// Scan state decays by prod(1/i): 16-step warm-up makes per-segment restarts
// exact to ~1e-20, so the scan parallelizes over all 256 threads.
// One block per row; b=0 normalized from the smem copy (read exactly once).
// Stream loads 5-deep cp.async ring (b=1..5 prefetched before the scan);
// each thread consumes only its own 16B slice -> no barriers in stream loop.
// Occupancy invariant: regs ~32, smem ~25KB -> still 8 CTAs/SM (reg-limited).

#define S_DIM 4096
#define D_DIM 1024
#define EPSV  1e-5f
#define WARM  16

__global__ __launch_bounds__(256)
void ln_fused_kernel(const float* __restrict__ x,
                     const float* __restrict__ alpha,
                     const float* __restrict__ beta,
                     float* __restrict__ out,
                     int B) {
    __shared__ float row[D_DIM + D_DIM / 32];           // swizzled row of x[0]
    __shared__ __align__(16) float stage[5][D_DIM];     // cp.async ring (20KB)
    __shared__ float s_part[8];
    __shared__ float s_stats[2];

    const int s   = blockIdx.x;
    const int tid = threadIdx.x;
    const size_t rowOff4 = (size_t)s * (D_DIM / 4) + tid;   // float4 index
    const float4* __restrict__ xf = (const float4*)x;

    const bool fast = (B == 8);
    if (fast) {
        // prefetch b=1..5 before the scan — latency hides under the prologue
#pragma unroll
        for (int bb = 1; bb <= 5; ++bb) {
            __pipeline_memcpy_async(&stage[bb - 1][tid * 4],
                                    xf + (size_t)bb * S_DIM * (D_DIM / 4) + rowOff4, 16);
            __pipeline_commit();
        }
    }

    // alpha/beta early — their latency also rides the prologue
    const float4 a = __ldg(((const float4*)alpha) + tid);
    const float4 b = __ldg(((const float4*)beta)  + tid);

    // ---- Phase 1: coalesced load of x[0,s,:] into swizzled smem ----
    {
        float4 v = __ldg(xf + rowOff4);
        int base = tid * 4;
        int o = base + (base >> 5);
        row[o]   = v.x; row[o+1] = v.y;
        row[o+2] = v.z; row[o+3] = v.w;
    }
    __syncthreads();

    // ---- Phase 2: all-thread segment-parallel scan (4 elems/thread) ----
    {
        const int start = tid * 4;
        const int wu    = (start < WARM) ? start : WARM;
        float m = 0.0f, v = 0.0f;

        for (int j = wu; j > 0; --j) {
            int idx = start - j;
            float d = row[idx + (idx >> 5)];
            float r = __fdividef(1.0f, (float)(idx + 1));
            m = fmaf(m, r, d * r);
        }
#pragma unroll
        for (int j = 0; j < 4; ++j) {
            int idx = start + j;
            float d = row[idx + (idx >> 5)];
            float r = __fdividef(1.0f, (float)(idx + 1));
            m = fmaf(m, r, d * r);               // (m + d)/i
            float t = d - m;
            v = fmaf(t, t, v);
        }
        if (tid == 255) s_stats[0] = m;

#pragma unroll
        for (int o = 16; o; o >>= 1)
            v += __shfl_xor_sync(0xffffffffu, v, o);
        if ((tid & 31) == 0) s_part[tid >> 5] = v;
        __syncthreads();
        if (tid == 0) {
            float vt = s_part[0] + s_part[1] + s_part[2] + s_part[3]
                     + s_part[4] + s_part[5] + s_part[6] + s_part[7];
            s_stats[1] = rsqrtf(vt / (float)(D_DIM - 1) + EPSV);
        }
    }
    __syncthreads();

    const float m  = s_stats[0];
    const float rs = s_stats[1];

    // ---- Phase 3a: b = 0 from the smem copy ----
    {
        int base = tid * 4;
        int o = base + (base >> 5);
        float4 ov;
        ov.x = fmaf((row[o]   - m) * rs, a.x, b.x);
        ov.y = fmaf((row[o+1] - m) * rs, a.y, b.y);
        ov.z = fmaf((row[o+2] - m) * rs, a.z, b.z);
        ov.w = fmaf((row[o+3] - m) * rs, a.w, b.w);
        __stcs(((float4*)out) + rowOff4, ov);
    }

    // ---- Phase 3b: stream b = 1..7 through the 5-deep cp.async ring ----
    if (fast) {
        // commits: b1..b5 pre-scan; refills b6,b7 at bb=1,2.
        // groups newer than bb at consume = min(4, 7-bb).
#pragma unroll
        for (int bb = 1; bb < 8; ++bb) {
            if      (bb <= 3) __pipeline_wait_prior(4);
            else if (bb == 4) __pipeline_wait_prior(3);
            else if (bb == 5) __pipeline_wait_prior(2);
            else if (bb == 6) __pipeline_wait_prior(1);
            else              __pipeline_wait_prior(0);

            float4 xv = *(const float4*)&stage[(bb - 1) % 5][tid * 4];

            if (bb + 5 < 8) {   // refill the slot just consumed (own slice only)
                __pipeline_memcpy_async(&stage[(bb - 1) % 5][tid * 4],
                                        xf + (size_t)(bb + 5) * S_DIM * (D_DIM / 4) + rowOff4, 16);
                __pipeline_commit();
            }

            float4 ov;
            ov.x = fmaf((xv.x - m) * rs, a.x, b.x);
            ov.y = fmaf((xv.y - m) * rs, a.y, b.y);
            ov.z = fmaf((xv.z - m) * rs, a.z, b.z);
            ov.w = fmaf((xv.w - m) * rs, a.w, b.w);
            __stcs(((float4*)out) + (size_t)bb * S_DIM * (D_DIM / 4) + rowOff4, ov);
        }
    } else {
        for (int bb = 1; bb < B; ++bb) {
            size_t idx = (size_t)bb * S_DIM * (D_DIM / 4) + rowOff4;
            float4 xv = __ldcs(xf + idx);
            float4 ov;
            ov.x = fmaf((xv.x - m) * rs, a.x, b.x);
            ov.y = fmaf((xv.y - m) * rs, a.y, b.y);
            ov.z = fmaf((xv.z - m) * rs, a.z, b.z);
            ov.w = fmaf((xv.w - m) * rs, a.w, b.w);
            __stcs(((float4*)out) + idx, ov);
        }
    }
}

extern "C" void kernel_launch(void* const* d_in, const int* in_sizes, int n_in,
                              void* d_out, int out_size) {
    const float* x     = (const float*)d_in[0];
    const float* alpha = (const float*)d_in[1];
    const float* beta  = (const float*)d_in[2];
    float*       out   = (float*)d_out;

    const int B = in_sizes[0] / (S_DIM * D_DIM);

    ln_fused_kernel<<<S_DIM, 256>>>(x, alpha, beta, out, B);
}